// round 10
// baseline (speedup 1.0000x reference)
#include <cuda_runtime.h>
#include <math.h>

#define NB   32
#define C    256
#define CI   64
#define L    6
#define T    64
#define V    50
#define K    3
#define EPSV 1e-5f

#define XT_ELEMS  (NB*C*L*V)
#define Y_ELEMS   (NB*CI*L*V)
#define OUT_ELEMS (NB*C*T*V)
#define MIDB 192

__device__ __align__(16) float g_xt[XT_ELEMS];
__device__ __align__(16) float g_WdT[C*CI];       // [c][d]
__device__ __align__(16) float g_y[Y_ELEMS];
__device__ __align__(16) float g_epre[NB*L*K*CI]; // [n][l][k][d]
__device__ float g_att[NB*C*L];
__device__ float g_s1[CI], g_q1[CI];
__device__ float g_s2[CI], g_q2[CI];
__device__ unsigned int g_bar0, g_bar1;

__constant__ int c_off[7] = {0, 6, 20, 42, 62, 78, 94};
__constant__ int c_layers[94] = {
    1, 0, 20, 26, 25, 45,
    0, 20, 12, 16, 2, 4, 8, 25, 45, 37, 41, 27, 29, 33,
    12, 16, 2, 4, 8, 13, 17, 3, 5, 9, 3, 28, 37, 41, 27, 29, 33, 38, 42, 28, 30, 34,
    13, 17, 3, 5, 9, 14, 18, 6, 10, 3, 28, 38, 42, 28, 30, 34, 39, 43, 31, 35,
    14, 18, 6, 10, 15, 19, 7, 11, 39, 43, 31, 35, 40, 44, 32, 36,
    15, 19, 7, 11, 21, 22, 23, 24, 40, 44, 32, 36, 46, 47, 48, 49
};

// ---------------------------------------------------------------------------
// K1: x_t = max over T (float2). Side: transpose W_down, zero sums + barriers.
// ---------------------------------------------------------------------------
__global__ void __launch_bounds__(256) k_maxT(const float* __restrict__ x,
                                              const float* __restrict__ Wd) {
    if (blockIdx.x < 64) {
        g_WdT[threadIdx.x * CI + blockIdx.x] = Wd[blockIdx.x * C + threadIdx.x];
    } else if (blockIdx.x == 64) {
        if (threadIdx.x < CI) {
            int t = threadIdx.x;
            g_s1[t] = 0.f; g_q1[t] = 0.f; g_s2[t] = 0.f; g_q2[t] = 0.f;
        }
        if (threadIdx.x == 64) { g_bar0 = 0u; g_bar1 = 0u; }
    }
    int i2 = blockIdx.x * 256 + threadIdx.x;
    if (i2 >= XT_ELEMS / 2) return;
    int v2  = i2 % (V / 2);
    int ncl = i2 / (V / 2);
    const float2* p = (const float2*)x + (size_t)ncl * (T * V / 2) + v2;
    float ax0 = -INFINITY, ay0 = -INFINITY, ax1 = -INFINITY, ay1 = -INFINITY;
    float ax2 = -INFINITY, ay2 = -INFINITY, ax3 = -INFINITY, ay3 = -INFINITY;
#pragma unroll
    for (int t = 0; t < T; t += 4) {
        float2 q0 = __ldg(p + (t + 0) * (V / 2));
        float2 q1 = __ldg(p + (t + 1) * (V / 2));
        float2 q2 = __ldg(p + (t + 2) * (V / 2));
        float2 q3 = __ldg(p + (t + 3) * (V / 2));
        ax0 = fmaxf(ax0, q0.x); ay0 = fmaxf(ay0, q0.y);
        ax1 = fmaxf(ax1, q1.x); ay1 = fmaxf(ay1, q1.y);
        ax2 = fmaxf(ax2, q2.x); ay2 = fmaxf(ay2, q2.y);
        ax3 = fmaxf(ax3, q3.x); ay3 = fmaxf(ay3, q3.y);
    }
    float2 r;
    r.x = fmaxf(fmaxf(ax0, ax1), fmaxf(ax2, ax3));
    r.y = fmaxf(fmaxf(ay0, ay1), fmaxf(ay2, ay3));
    ((float2*)g_xt)[i2] = r;
}

// ---------------------------------------------------------------------------
// Software grid barrier (all MIDB blocks resident: 3/SM by smem, 4/SM by thr).
// ---------------------------------------------------------------------------
__device__ __forceinline__ void grid_barrier(unsigned int* bar) {
    __syncthreads();
    if (threadIdx.x == 0) {
        __threadfence();
        atomicAdd(bar, 1u);
        volatile unsigned int* vb = bar;
        while (*vb < MIDB) { }
        __threadfence();
    }
    __syncthreads();
}

// ---------------------------------------------------------------------------
// K2 merged middle. Grid 192, block 512.
// Phase A: down-GEMM per (n,l)   — all 192 blocks (identical to split kernel)
// Phase B: graph per (n,half)    — blocks 0..63
// Phase C: att per (n,l)         — all 192 blocks
// ---------------------------------------------------------------------------
__global__ void __launch_bounds__(512) k_mid(const float* __restrict__ bd,
                                             const float* __restrict__ g1,
                                             const float* __restrict__ b1,
                                             const float* __restrict__ We,
                                             const float* __restrict__ g2,
                                             const float* __restrict__ b2,
                                             const float* __restrict__ Wa,
                                             const float* __restrict__ ba) {
    __shared__ __align__(16) float sm[14592];   // 57 KB, re-carved per phase
    __shared__ int sidx[L * K];
    int tid = threadIdx.x;

    // ---------------- Phase A: down-proj GEMM (n,l) = blockIdx -------------
    {
        int n = blockIdx.x / L;
        int l = blockIdx.x % L;
        float* sW = sm;            // [128][64] = 8192
        float* sx = sm + 8192;     // [128][50] = 6400
        int v = tid % V;
        int dg = tid / V;
        float acc[8];
#pragma unroll
        for (int i = 0; i < 8; i++) acc[i] = 0.f;
        for (int ch = 0; ch < 2; ch++) {
            int cb = ch * 128;
            const float4* Wg = (const float4*)(g_WdT + cb * CI);
            float4* sW4 = (float4*)sW;
            for (int j = tid; j < 2048; j += 512) sW4[j] = __ldg(Wg + j);
            for (int j = tid; j < 3200; j += 512) {
                int cl = j / 25, v2 = j % 25;
                ((float2*)sx)[cl * 25 + v2] =
                    *(const float2*)(g_xt + (size_t)(n * C + cb + cl) * (L * V) + l * V + v2 * 2);
            }
            __syncthreads();
            if (tid < 400) {
#pragma unroll 8
                for (int cl = 0; cl < 128; cl++) {
                    float xv = sx[cl * V + v];
                    const float4* w4 = (const float4*)(sW + cl * 64 + dg * 8);
                    float4 w0 = w4[0], w1 = w4[1];
                    acc[0] += w0.x * xv; acc[1] += w0.y * xv; acc[2] += w0.z * xv; acc[3] += w0.w * xv;
                    acc[4] += w1.x * xv; acc[5] += w1.y * xv; acc[6] += w1.z * xv; acc[7] += w1.w * xv;
                }
            }
            __syncthreads();
        }
        if (tid < 400) {
#pragma unroll
            for (int i = 0; i < 8; i++) {
                int d = dg * 8 + i;
                float yv = acc[i] + __ldg(&bd[d]);
                g_y[((n * CI + d) * L + l) * V + v] = yv;
                sx[d * V + v] = yv;
            }
        }
        __syncthreads();
        if (tid < CI) {
            float s = 0.f, q = 0.f;
#pragma unroll
            for (int vv = 0; vv < V; vv++) {
                float yv = sx[tid * V + vv];
                s += yv; q += yv * yv;
            }
            atomicAdd(&g_s1[tid], s);
            atomicAdd(&g_q1[tid], q);
        }
    }

    grid_barrier(&g_bar0);

    // ---------------- Phase B: graph, blocks 0..63 = (n, half) -------------
    if (blockIdx.x < 64) {
        int n = blockIdx.x >> 1;
        int half = blockIdx.x & 1;
        float* sWe   = sm;                     // 8256
        float* sxs   = sm + 8256;              // 384
        float* sstat = sm + 8640;              // 128
        float* sinn  = sm + 8768;              // 64 (36 used)
        float* sredp = sm + 8832;              // 192
        float* sredq = sm + 9024;              // 192
        int d = tid & 63;
        int lf = tid / 64;

        const float4* We4 = (const float4*)We;
        for (int j = tid; j < 2048; j += 512) {
            float4 w = __ldg(We4 + j);
            int dd = j >> 5, c4 = (j & 31) * 4;
            float* p = &sWe[dd * 129 + c4];
            p[0] = w.x; p[1] = w.y; p[2] = w.z; p[3] = w.w;
        }
        if (tid < CI) {
            float s = g_s1[tid], q = g_q1[tid];
            float cnt = (float)(NB * L * V);
            float mean = s / cnt;
            float var  = q / cnt - mean * mean;
            sstat[tid]      = mean;
            sstat[CI + tid] = rsqrtf(var + EPSV);
        }
        __syncthreads();

        if (tid < 384) {
            float mean = sstat[d], rstd = sstat[CI + d];
            float gm = __ldg(&g1[d]), bt = __ldg(&b1[d]);
            int base = (n * CI + d) * (L * V) + lf * V;
            int o0 = c_off[lf], o1 = c_off[lf + 1];
            float s = 0.f;
            for (int j = o0; j < o1; j++) {
                float yv = (__ldg(&g_y[base + c_layers[j]]) - mean) * rstd * gm + bt;
                s += fmaxf(yv, 0.f);
            }
            sxs[d * L + lf] = s / (float)(o1 - o0);
        }
        __syncthreads();

        if (tid < L * L) {
            int ll = tid / L, mm = tid % L;
            float s = 0.f;
            for (int c = 0; c < CI; c++) s += sxs[c * L + ll] * sxs[c * L + mm];
            sinn[tid] = s;
        }
        __syncthreads();
        if (tid < L) {
            int taken = 0;
            float xl = sinn[tid * L + tid];
            for (int k = 0; k < K; k++) {
                int best = -1; float bv = -INFINITY;
                for (int m = 0; m < L; m++) {
                    if ((taken >> m) & 1) continue;
                    float pv = 2.f * sinn[tid * L + m] - xl - sinn[m * L + m];
                    if (pv > bv) { bv = pv; best = m; }
                }
                taken |= (1 << best);
                sidx[tid * K + k] = best;
            }
        }
        __syncthreads();

        if (tid < 192) {
            int l3 = tid / 64;
            int l = half * 3 + l3;
            int i0 = sidx[l * K + 0], i1 = sidx[l * K + 1], i2 = sidx[l * K + 2];
            float a0 = 0.f, a1 = 0.f, a2 = 0.f;
#pragma unroll 4
            for (int c = 0; c < CI; c++) {
                float wa = sWe[d * 129 + c];
                float wb = sWe[d * 129 + CI + c];
                float ctr = sxs[c * L + l];
                float base = (wb - wa) * ctr;
                a0 += wa * sxs[c * L + i0] + base;
                a1 += wa * sxs[c * L + i1] + base;
                a2 += wa * sxs[c * L + i2] + base;
            }
            int ob = (n * L + l) * K * CI + d;
            g_epre[ob + 0 * CI] = a0;
            g_epre[ob + 1 * CI] = a1;
            g_epre[ob + 2 * CI] = a2;
            sredp[l3 * CI + d] = a0 + a1 + a2;
            sredq[l3 * CI + d] = a0 * a0 + a1 * a1 + a2 * a2;
        }
        __syncthreads();
        if (tid < CI) {
            float s = 0.f, q = 0.f;
#pragma unroll
            for (int l3 = 0; l3 < 3; l3++) {
                s += sredp[l3 * CI + tid];
                q += sredq[l3 * CI + tid];
            }
            atomicAdd(&g_s2[tid], s);
            atomicAdd(&g_q2[tid], q);
        }
    }

    grid_barrier(&g_bar1);

    // ---------------- Phase C: attention, (n,l) = blockIdx -----------------
    {
        int n = blockIdx.x / L;
        int l = blockIdx.x % L;
        float* se = sm;                        // 64
        if (tid < CI) {
            int d = tid;
            float s = g_s2[d], q = g_q2[d];
            float cnt = (float)(NB * L * K);
            float mean = s / cnt;
            float rstd = rsqrtf(q / cnt - mean * mean + EPSV);
            float gm = __ldg(&g2[d]), bt = __ldg(&b2[d]);
            int base = (n * L + l) * K * CI + d;
            float e0 = g_epre[base + 0 * CI];
            float e1 = g_epre[base + 1 * CI];
            float e2 = g_epre[base + 2 * CI];
            float mx = -INFINITY, ev;
            ev = (e0 - mean) * rstd * gm + bt; ev = (ev >= 0.f) ? ev : 0.2f * ev; mx = fmaxf(mx, ev);
            ev = (e1 - mean) * rstd * gm + bt; ev = (ev >= 0.f) ? ev : 0.2f * ev; mx = fmaxf(mx, ev);
            ev = (e2 - mean) * rstd * gm + bt; ev = (ev >= 0.f) ? ev : 0.2f * ev; mx = fmaxf(mx, ev);
            se[d] = mx;
        }
        __syncthreads();
        if (tid < 256) {
            float acc = 0.f;
            const float4* Wa4 = (const float4*)(Wa + tid * CI);
            const float4* se4 = (const float4*)se;
#pragma unroll
            for (int j = 0; j < 16; j++) {
                float4 w = __ldg(Wa4 + j);
                float4 e = se4[j];
                acc += w.x * e.x + w.y * e.y + w.z * e.z + w.w * e.w;
            }
            float a = acc + __ldg(&ba[tid]);
            g_att[(n * C + tid) * L + l] = 1.f / (1.f + __expf(-a));
        }
    }
}

// ---------------------------------------------------------------------------
// K3: out = sum_l x*att. 2 float4 per thread (R7 proven form).
// ---------------------------------------------------------------------------
__global__ void __launch_bounds__(256) k_out(const float* __restrict__ x,
                                             float* __restrict__ out) {
    int base = blockIdx.x * 512 + threadIdx.x;
#pragma unroll
    for (int r = 0; r < 2; r++) {
        int i4 = base + r * 256;
        if (i4 >= OUT_ELEMS / 4) return;
        int tv4 = i4 % (T * V / 4);
        int nc  = i4 / (T * V / 4);
        const float4* px = (const float4*)x + (size_t)nc * (L * T * V / 4) + tv4;
        float a0 = __ldg(&g_att[nc * L + 0]);
        float a1 = __ldg(&g_att[nc * L + 1]);
        float a2 = __ldg(&g_att[nc * L + 2]);
        float a3 = __ldg(&g_att[nc * L + 3]);
        float a4 = __ldg(&g_att[nc * L + 4]);
        float a5 = __ldg(&g_att[nc * L + 5]);
        float4 x0 = __ldg(px + 0 * 800);
        float4 x1 = __ldg(px + 1 * 800);
        float4 x2 = __ldg(px + 2 * 800);
        float4 x3 = __ldg(px + 3 * 800);
        float4 x4 = __ldg(px + 4 * 800);
        float4 x5 = __ldg(px + 5 * 800);
        float4 rr;
        rr.x = a0*x0.x + a1*x1.x + a2*x2.x + a3*x3.x + a4*x4.x + a5*x5.x;
        rr.y = a0*x0.y + a1*x1.y + a2*x2.y + a3*x3.y + a4*x4.y + a5*x5.y;
        rr.z = a0*x0.z + a1*x1.z + a2*x2.z + a3*x3.z + a4*x4.z + a5*x5.z;
        rr.w = a0*x0.w + a1*x1.w + a2*x2.w + a3*x3.w + a4*x4.w + a5*x5.w;
        ((float4*)out)[i4] = rr;
    }
}

// ---------------------------------------------------------------------------
extern "C" void kernel_launch(void* const* d_in, const int* in_sizes, int n_in,
                              void* d_out, int out_size) {
    const float* x      = (const float*)d_in[0];
    const float* W_down = (const float*)d_in[1];
    const float* b_down = (const float*)d_in[2];
    const float* gamma1 = (const float*)d_in[3];
    const float* beta1  = (const float*)d_in[4];
    const float* W_edge = (const float*)d_in[5];
    const float* gamma2 = (const float*)d_in[6];
    const float* beta2  = (const float*)d_in[7];
    const float* W_agg  = (const float*)d_in[8];
    const float* b_agg  = (const float*)d_in[9];
    float* out = (float*)d_out;

    k_maxT<<<(XT_ELEMS / 2 + 255) / 256, 256>>>(x, W_down);
    k_mid<<<MIDB, 512>>>(b_down, gamma1, beta1, W_edge,
                         gamma2, beta2, W_agg, b_agg);
    k_out<<<(OUT_ELEMS / 4 + 511) / 512, 256>>>(x, out);
}

// round 11
// speedup vs baseline: 1.0958x; 1.0958x over previous
#include <cuda_runtime.h>
#include <math.h>

#define NB   32
#define C    256
#define CI   64
#define L    6
#define T    64
#define V    50
#define K    3
#define EPSV 1e-5f

#define XT_ELEMS  (NB*C*L*V)
#define Y_ELEMS   (NB*CI*L*V)
#define OUT_ELEMS (NB*C*T*V)

__device__ __align__(16) float g_xt[XT_ELEMS];
__device__ __align__(16) float g_WdT[C*CI];       // [c][d]
__device__ __align__(16) float g_y[Y_ELEMS];
__device__ __align__(16) float g_epre[NB*L*K*CI]; // [n][l][k][d]
__device__ float g_att[NB*C*L];
__device__ float g_s1[CI], g_q1[CI];
__device__ float g_s2[CI], g_q2[CI];

__constant__ int c_off[7] = {0, 6, 20, 42, 62, 78, 94};
__constant__ int c_layers[94] = {
    1, 0, 20, 26, 25, 45,
    0, 20, 12, 16, 2, 4, 8, 25, 45, 37, 41, 27, 29, 33,
    12, 16, 2, 4, 8, 13, 17, 3, 5, 9, 3, 28, 37, 41, 27, 29, 33, 38, 42, 28, 30, 34,
    13, 17, 3, 5, 9, 14, 18, 6, 10, 3, 28, 38, 42, 28, 30, 34, 39, 43, 31, 35,
    14, 18, 6, 10, 15, 19, 7, 11, 39, 43, 31, 35, 40, 44, 32, 36,
    15, 19, 7, 11, 21, 22, 23, 24, 40, 44, 32, 36, 46, 47, 48, 49
};

// ---------------------------------------------------------------------------
// K1: x_t = max over T (float2). Side jobs: transpose W_down, zero BN sums.
// ---------------------------------------------------------------------------
__global__ void __launch_bounds__(256) k_maxT(const float* __restrict__ x,
                                              const float* __restrict__ Wd) {
    if (blockIdx.x < 64) {
        g_WdT[threadIdx.x * CI + blockIdx.x] = Wd[blockIdx.x * C + threadIdx.x];
    } else if (blockIdx.x == 64 && threadIdx.x < CI) {
        int t = threadIdx.x;
        g_s1[t] = 0.f; g_q1[t] = 0.f; g_s2[t] = 0.f; g_q2[t] = 0.f;
    }
    int i2 = blockIdx.x * 256 + threadIdx.x;
    if (i2 >= XT_ELEMS / 2) return;
    int v2  = i2 % (V / 2);
    int ncl = i2 / (V / 2);
    const float2* p = (const float2*)x + (size_t)ncl * (T * V / 2) + v2;
    float ax0 = -INFINITY, ay0 = -INFINITY, ax1 = -INFINITY, ay1 = -INFINITY;
    float ax2 = -INFINITY, ay2 = -INFINITY, ax3 = -INFINITY, ay3 = -INFINITY;
#pragma unroll
    for (int t = 0; t < T; t += 4) {
        float2 q0 = __ldg(p + (t + 0) * (V / 2));
        float2 q1 = __ldg(p + (t + 1) * (V / 2));
        float2 q2 = __ldg(p + (t + 2) * (V / 2));
        float2 q3 = __ldg(p + (t + 3) * (V / 2));
        ax0 = fmaxf(ax0, q0.x); ay0 = fmaxf(ay0, q0.y);
        ax1 = fmaxf(ax1, q1.x); ay1 = fmaxf(ay1, q1.y);
        ax2 = fmaxf(ax2, q2.x); ay2 = fmaxf(ay2, q2.y);
        ax3 = fmaxf(ax3, q3.x); ay3 = fmaxf(ay3, q3.y);
    }
    float2 r;
    r.x = fmaxf(fmaxf(ax0, ax1), fmaxf(ax2, ax3));
    r.y = fmaxf(fmaxf(ay0, ay1), fmaxf(ay2, ay3));
    ((float2*)g_xt)[i2] = r;
}

// ---------------------------------------------------------------------------
// K2: y = W_down @ xt + b (PDL). Block per (n,l)=192, 512 threads.
// ---------------------------------------------------------------------------
__global__ void __launch_bounds__(512) k_down(const float* __restrict__ bd) {
    cudaGridDependencySynchronize();     // needs g_WdT and g_xt
    int n = blockIdx.x / L;
    int l = blockIdx.x % L;
    __shared__ __align__(16) float sW[128 * 64];
    __shared__ __align__(16) float sx[128 * V];
    int tid = threadIdx.x;
    int v = tid % V;
    int dg = tid / V;
    float acc[8];
#pragma unroll
    for (int i = 0; i < 8; i++) acc[i] = 0.f;

    for (int ch = 0; ch < 2; ch++) {
        int cb = ch * 128;
        const float4* Wg = (const float4*)(g_WdT + cb * CI);
        float4* sW4 = (float4*)sW;
        for (int j = tid; j < 2048; j += 512) sW4[j] = __ldg(Wg + j);
        for (int j = tid; j < 3200; j += 512) {
            int cl = j / 25, v2 = j % 25;
            ((float2*)sx)[cl * 25 + v2] =
                *(const float2*)(g_xt + (size_t)(n * C + cb + cl) * (L * V) + l * V + v2 * 2);
        }
        __syncthreads();
        if (tid < 400) {
#pragma unroll 8
            for (int cl = 0; cl < 128; cl++) {
                float xv = sx[cl * V + v];
                const float4* w4 = (const float4*)(sW + cl * 64 + dg * 8);
                float4 w0 = w4[0], w1 = w4[1];
                acc[0] += w0.x * xv; acc[1] += w0.y * xv; acc[2] += w0.z * xv; acc[3] += w0.w * xv;
                acc[4] += w1.x * xv; acc[5] += w1.y * xv; acc[6] += w1.z * xv; acc[7] += w1.w * xv;
            }
        }
        __syncthreads();
    }
    if (tid < 400) {
#pragma unroll
        for (int i = 0; i < 8; i++) {
            int d = dg * 8 + i;
            float yv = acc[i] + __ldg(&bd[d]);
            g_y[((n * CI + d) * L + l) * V + v] = yv;
            sx[d * V + v] = yv;
        }
    }
    __syncthreads();
    if (tid < CI) {
        float s = 0.f, q = 0.f;
#pragma unroll
        for (int vv = 0; vv < V; vv++) {
            float yv = sx[tid * V + vv];
            s += yv; q += yv * yv;
        }
        atomicAdd(&g_s1[tid], s);
        atomicAdd(&g_q1[tid], q);
    }
}

// ---------------------------------------------------------------------------
// K3 (PDL): BN1-finalize + xs + topk + edge GEMM + BN2 partials.
// Grid 64 = (n, half). 384 threads. W_edge staged to smem BEFORE gridDepSync.
// ---------------------------------------------------------------------------
__global__ void __launch_bounds__(384) k_graph(const float* __restrict__ g1,
                                               const float* __restrict__ b1,
                                               const float* __restrict__ We) {
    int n = blockIdx.x >> 1;
    int half = blockIdx.x & 1;
    int tid = threadIdx.x;
    int d = tid & 63;
    int lf = tid / 64;
    __shared__ float sWe[CI * 129];
    __shared__ float sxs[CI * L];
    __shared__ float sstat[2 * CI];
    __shared__ float sinn[L * L];
    __shared__ int   sidx[L * K];
    __shared__ float sredp[3 * CI], sredq[3 * CI];

    // Independent prologue: stage W_edge (input) while predecessor drains.
    const float4* We4 = (const float4*)We;
    for (int j = tid; j < 2048; j += 384) {
        float4 w = __ldg(We4 + j);
        int dd = j >> 5, c4 = (j & 31) * 4;
        float* p = &sWe[dd * 129 + c4];
        p[0] = w.x; p[1] = w.y; p[2] = w.z; p[3] = w.w;
    }
    float gm_r = __ldg(&g1[d]), bt_r = __ldg(&b1[d]);

    cudaGridDependencySynchronize();     // needs g_s1/g_q1/g_y

    if (tid < CI) {
        float s = g_s1[tid], q = g_q1[tid];
        float cnt = (float)(NB * L * V);
        float mean = s / cnt;
        float var  = q / cnt - mean * mean;
        sstat[tid]      = mean;
        sstat[CI + tid] = rsqrtf(var + EPSV);
    }
    __syncthreads();

    {
        float mean = sstat[d], rstd = sstat[CI + d];
        int base = (n * CI + d) * (L * V) + lf * V;
        int o0 = c_off[lf], o1 = c_off[lf + 1];
        float s = 0.f;
        for (int j = o0; j < o1; j++) {
            float yv = (__ldg(&g_y[base + c_layers[j]]) - mean) * rstd * gm_r + bt_r;
            s += fmaxf(yv, 0.f);
        }
        sxs[d * L + lf] = s / (float)(o1 - o0);
    }
    __syncthreads();

    if (tid < L * L) {
        int ll = tid / L, mm = tid % L;
        float s = 0.f;
        for (int c = 0; c < CI; c++) s += sxs[c * L + ll] * sxs[c * L + mm];
        sinn[tid] = s;
    }
    __syncthreads();
    if (tid < L) {
        int taken = 0;
        float xl = sinn[tid * L + tid];
        for (int k = 0; k < K; k++) {
            int best = -1; float bv = -INFINITY;
            for (int m = 0; m < L; m++) {
                if ((taken >> m) & 1) continue;
                float pv = 2.f * sinn[tid * L + m] - xl - sinn[m * L + m];
                if (pv > bv) { bv = pv; best = m; }
            }
            taken |= (1 << best);
            sidx[tid * K + k] = best;
        }
    }
    __syncthreads();

    if (tid < 192) {
        int l3 = tid / 64;
        int l = half * 3 + l3;
        int i0 = sidx[l * K + 0], i1 = sidx[l * K + 1], i2 = sidx[l * K + 2];
        float a0 = 0.f, a1 = 0.f, a2 = 0.f;
#pragma unroll 4
        for (int c = 0; c < CI; c++) {
            float wa = sWe[d * 129 + c];
            float wb = sWe[d * 129 + CI + c];
            float ctr = sxs[c * L + l];
            float base = (wb - wa) * ctr;
            a0 += wa * sxs[c * L + i0] + base;
            a1 += wa * sxs[c * L + i1] + base;
            a2 += wa * sxs[c * L + i2] + base;
        }
        int ob = (n * L + l) * K * CI + d;
        g_epre[ob + 0 * CI] = a0;
        g_epre[ob + 1 * CI] = a1;
        g_epre[ob + 2 * CI] = a2;
        sredp[l3 * CI + d] = a0 + a1 + a2;
        sredq[l3 * CI + d] = a0 * a0 + a1 * a1 + a2 * a2;
    }
    __syncthreads();
    if (tid < CI) {
        float s = 0.f, q = 0.f;
#pragma unroll
        for (int l3 = 0; l3 < 3; l3++) {
            s += sredp[l3 * CI + tid];
            q += sredq[l3 * CI + tid];
        }
        atomicAdd(&g_s2[tid], s);
        atomicAdd(&g_q2[tid], q);
    }
}

// ---------------------------------------------------------------------------
// K4 (PDL): BN2-finalize + e + att. Block per (n,l) = 192. Wa preloaded
// into registers BEFORE gridDepSync.
// ---------------------------------------------------------------------------
__global__ void __launch_bounds__(256) k_att(const float* __restrict__ g2,
                                             const float* __restrict__ b2,
                                             const float* __restrict__ Wa,
                                             const float* __restrict__ ba) {
    int n = blockIdx.x / L;
    int l = blockIdx.x % L;
    int tid = threadIdx.x;
    __shared__ __align__(16) float se[CI];

    // Independent prologue (inputs only)
    float4 wreg[16];
    const float4* Wa4 = (const float4*)(Wa + tid * CI);
#pragma unroll
    for (int j = 0; j < 16; j++) wreg[j] = __ldg(Wa4 + j);
    float bb = __ldg(&ba[tid]);
    float gm = 0.f, bt = 0.f;
    if (tid < CI) { gm = __ldg(&g2[tid]); bt = __ldg(&b2[tid]); }

    cudaGridDependencySynchronize();     // needs g_s2/g_q2/g_epre

    if (tid < CI) {
        int d = tid;
        float s = g_s2[d], q = g_q2[d];
        float cnt = (float)(NB * L * K);
        float mean = s / cnt;
        float rstd = rsqrtf(q / cnt - mean * mean + EPSV);
        int base = (n * L + l) * K * CI + d;
        float e0 = __ldg(&g_epre[base + 0 * CI]);
        float e1 = __ldg(&g_epre[base + 1 * CI]);
        float e2 = __ldg(&g_epre[base + 2 * CI]);
        float mx = -INFINITY, ev;
        ev = (e0 - mean) * rstd * gm + bt; ev = (ev >= 0.f) ? ev : 0.2f * ev; mx = fmaxf(mx, ev);
        ev = (e1 - mean) * rstd * gm + bt; ev = (ev >= 0.f) ? ev : 0.2f * ev; mx = fmaxf(mx, ev);
        ev = (e2 - mean) * rstd * gm + bt; ev = (ev >= 0.f) ? ev : 0.2f * ev; mx = fmaxf(mx, ev);
        se[d] = mx;
    }
    __syncthreads();
    float acc = 0.f;
    const float4* se4 = (const float4*)se;
#pragma unroll
    for (int j = 0; j < 16; j++) {
        float4 w = wreg[j];
        float4 e = se4[j];
        acc += w.x * e.x + w.y * e.y + w.z * e.z + w.w * e.w;
    }
    float a = acc + bb;
    g_att[(n * C + tid) * L + l] = 1.f / (1.f + __expf(-a));
}

// ---------------------------------------------------------------------------
// K5 (PDL): out = sum_l x*att. First iteration's x loads issued BEFORE
// gridDepSync (x is an input, independent of predecessors).
// ---------------------------------------------------------------------------
__global__ void __launch_bounds__(256) k_out(const float* __restrict__ x,
                                             float* __restrict__ out) {
    int base = blockIdx.x * 512 + threadIdx.x;
    const float4* x4b = (const float4*)x;

    // Prefetch r=0 slice of x before waiting on att
    int i4a = base;
    int tv4a = i4a % (T * V / 4);
    int nca  = i4a / (T * V / 4);
    const float4* pa = x4b + (size_t)nca * (L * T * V / 4) + tv4a;
    float4 p0 = __ldg(pa + 0 * 800);
    float4 p1 = __ldg(pa + 1 * 800);
    float4 p2 = __ldg(pa + 2 * 800);
    float4 p3 = __ldg(pa + 3 * 800);
    float4 p4 = __ldg(pa + 4 * 800);
    float4 p5 = __ldg(pa + 5 * 800);

    cudaGridDependencySynchronize();     // needs g_att

    {
        float a0 = __ldg(&g_att[nca * L + 0]);
        float a1 = __ldg(&g_att[nca * L + 1]);
        float a2 = __ldg(&g_att[nca * L + 2]);
        float a3 = __ldg(&g_att[nca * L + 3]);
        float a4 = __ldg(&g_att[nca * L + 4]);
        float a5 = __ldg(&g_att[nca * L + 5]);
        float4 rr;
        rr.x = a0*p0.x + a1*p1.x + a2*p2.x + a3*p3.x + a4*p4.x + a5*p5.x;
        rr.y = a0*p0.y + a1*p1.y + a2*p2.y + a3*p3.y + a4*p4.y + a5*p5.y;
        rr.z = a0*p0.z + a1*p1.z + a2*p2.z + a3*p3.z + a4*p4.z + a5*p5.z;
        rr.w = a0*p0.w + a1*p1.w + a2*p2.w + a3*p3.w + a4*p4.w + a5*p5.w;
        ((float4*)out)[i4a] = rr;
    }
    {
        int i4 = base + 256;
        if (i4 >= OUT_ELEMS / 4) return;
        int tv4 = i4 % (T * V / 4);
        int nc  = i4 / (T * V / 4);
        const float4* px = x4b + (size_t)nc * (L * T * V / 4) + tv4;
        float a0 = __ldg(&g_att[nc * L + 0]);
        float a1 = __ldg(&g_att[nc * L + 1]);
        float a2 = __ldg(&g_att[nc * L + 2]);
        float a3 = __ldg(&g_att[nc * L + 3]);
        float a4 = __ldg(&g_att[nc * L + 4]);
        float a5 = __ldg(&g_att[nc * L + 5]);
        float4 x0 = __ldg(px + 0 * 800);
        float4 x1 = __ldg(px + 1 * 800);
        float4 x2 = __ldg(px + 2 * 800);
        float4 x3 = __ldg(px + 3 * 800);
        float4 x4 = __ldg(px + 4 * 800);
        float4 x5 = __ldg(px + 5 * 800);
        float4 rr;
        rr.x = a0*x0.x + a1*x1.x + a2*x2.x + a3*x3.x + a4*x4.x + a5*x5.x;
        rr.y = a0*x0.y + a1*x1.y + a2*x2.y + a3*x3.y + a4*x4.y + a5*x5.y;
        rr.z = a0*x0.z + a1*x1.z + a2*x2.z + a3*x3.z + a4*x4.z + a5*x5.z;
        rr.w = a0*x0.w + a1*x1.w + a2*x2.w + a3*x3.w + a4*x4.w + a5*x5.w;
        ((float4*)out)[i4] = rr;
    }
}

// ---------------------------------------------------------------------------
template <typename F, typename... Args>
static void launch_pdl(F func, dim3 grid, dim3 block, Args... args) {
    cudaLaunchConfig_t cfg = {};
    cfg.gridDim = grid;
    cfg.blockDim = block;
    cfg.stream = 0;
    cudaLaunchAttribute attr[1];
    attr[0].id = cudaLaunchAttributeProgrammaticStreamSerialization;
    attr[0].val.programmaticStreamSerializationAllowed = 1;
    cfg.attrs = attr;
    cfg.numAttrs = 1;
    cudaLaunchKernelEx(&cfg, func, args...);
}

extern "C" void kernel_launch(void* const* d_in, const int* in_sizes, int n_in,
                              void* d_out, int out_size) {
    const float* x      = (const float*)d_in[0];
    const float* W_down = (const float*)d_in[1];
    const float* b_down = (const float*)d_in[2];
    const float* gamma1 = (const float*)d_in[3];
    const float* beta1  = (const float*)d_in[4];
    const float* W_edge = (const float*)d_in[5];
    const float* gamma2 = (const float*)d_in[6];
    const float* beta2  = (const float*)d_in[7];
    const float* W_agg  = (const float*)d_in[8];
    const float* b_agg  = (const float*)d_in[9];
    float* out = (float*)d_out;

    k_maxT<<<(XT_ELEMS / 2 + 255) / 256, 256>>>(x, W_down);
    launch_pdl(k_down,  dim3(NB * L), dim3(512), b_down);
    launch_pdl(k_graph, dim3(NB * 2), dim3(384), gamma1, beta1, W_edge);
    launch_pdl(k_att,   dim3(NB * L), dim3(256), gamma2, beta2, W_agg, b_agg);
    launch_pdl(k_out,   dim3((OUT_ELEMS / 4 + 511) / 512), dim3(256), x, out);
}